// round 7
// baseline (speedup 1.0000x reference)
#include <cuda_runtime.h>

// ---------------- constants ----------------
#define TOTHW   16800
#define CLSBASE 0
#define REGBASE 2688000   // 8*16800*20
#define CTRBASE 3225600   // + 8*16800*4

// scratch (device globals: allocation-free rule). Referenced directly from
// device code — kernel_launch performs NO runtime API calls except launches.
__device__ float g_bufA[26214400];   // 8*256*100*128
__device__ float g_bufB[26214400];
__device__ float g_sa[2048];         // per (n,c) GN scale
__device__ float g_sb[2048];         // per (n,c) GN shift

// ---------------- 3x3 conv 256->256 ----------------
// block: 128 threads = 32 lanes (4 consecutive co each) x 4 pixel-groups (8 px each)
// grid: (N*H*(W/32), 2)  -> 2 co-tiles of 128
// MODE 0: raw input from arg, write g_bufA
// MODE 1: input = relu(g_sa*x + g_sb) from g_bufA, write g_bufB
template<int MODE>
__global__ __launch_bounds__(128)
void conv_cc(const float* __restrict__ inArg, const float* __restrict__ w,
             const float* __restrict__ bias, int H, int W)
{
    const float* __restrict__ in  = (MODE == 0) ? inArg : g_bufA;
    float* __restrict__       out = (MODE == 0) ? g_bufA : g_bufB;

    __shared__ float4 wt4[72 * 32];      // [k=ci*9+kh*3+kw][lane] -> float4 over 4 co
    __shared__ float  in_s[8 * 3 * 36];  // [ci][row][34 cols + pad]
    float* wt = reinterpret_cast<float*>(wt4);

    const int tid  = threadIdx.x;
    const int lane = tid & 31;
    const int pg   = tid >> 5;
    const int tilesW   = W >> 5;
    const int tilesImg = H * tilesW;
    const int n   = blockIdx.x / tilesImg;
    int rem       = blockIdx.x - n * tilesImg;
    const int h   = rem / tilesW;
    const int w0  = (rem - h * tilesW) << 5;
    const int coBase = blockIdx.y << 7;

    float acc[4][8];
#pragma unroll
    for (int a = 0; a < 4; a++)
#pragma unroll
        for (int b = 0; b < 8; b++) acc[a][b] = 0.f;

#pragma unroll 1
    for (int ch = 0; ch < 32; ch++) {
        const int c0 = ch << 3;
        __syncthreads();
        // stage weights: each thread streams 72 contiguous floats of its own co row
        {
            const float4* wg = reinterpret_cast<const float4*>(
                w + (size_t)(coBase + tid) * 2304 + c0 * 9);
#pragma unroll
            for (int m = 0; m < 18; m++) {
                float4 v = wg[m];
                wt[(4*m + 0) * 128 + tid] = v.x;
                wt[(4*m + 1) * 128 + tid] = v.y;
                wt[(4*m + 2) * 128 + tid] = v.z;
                wt[(4*m + 3) * 128 + tid] = v.w;
            }
        }
        // stage input halo (with fused GN+ReLU when MODE==1)
#pragma unroll 1
        for (int i = tid; i < 816; i += 128) {
            int ci = i / 102; int r2 = i - ci * 102;
            int rr = r2 / 34;  int cc = r2 - rr * 34;
            int hin = h + rr - 1;
            int win = w0 + cc - 1;
            float v = 0.f;
            if ((unsigned)hin < (unsigned)H && (unsigned)win < (unsigned)W) {
                v = in[((size_t)(n * 256 + c0 + ci) * H + hin) * W + win];
                if (MODE == 1) {
                    int cx = n * 256 + c0 + ci;
                    v = fmaxf(0.f, fmaf(g_sa[cx], v, g_sb[cx]));
                }
            }
            in_s[(ci * 3 + rr) * 36 + cc] = v;
        }
        __syncthreads();
        // compute
#pragma unroll 1
        for (int ci = 0; ci < 8; ci++) {
#pragma unroll
            for (int kh = 0; kh < 3; kh++) {
                const float* row = &in_s[(ci * 3 + kh) * 36 + pg * 8];
                float r[10];
#pragma unroll
                for (int x = 0; x < 10; x++) r[x] = row[x];
#pragma unroll
                for (int kw = 0; kw < 3; kw++) {
                    float4 wv = wt4[(ci * 9 + kh * 3 + kw) * 32 + lane];
#pragma unroll
                    for (int j = 0; j < 8; j++) {
                        float iv = r[j + kw];
                        acc[0][j] = fmaf(wv.x, iv, acc[0][j]);
                        acc[1][j] = fmaf(wv.y, iv, acc[1][j]);
                        acc[2][j] = fmaf(wv.z, iv, acc[2][j]);
                        acc[3][j] = fmaf(wv.w, iv, acc[3][j]);
                    }
                }
            }
        }
    }
    __syncthreads();
    // stage output through smem (reuse weight buffer) for coalesced NCHW stores
    float* so = wt;
#pragma unroll
    for (int cc2 = 0; cc2 < 4; cc2++) {
        float bv = bias[coBase + 4 * lane + cc2];
#pragma unroll
        for (int j = 0; j < 8; j++)
            so[(4 * lane + cc2) * 36 + pg * 8 + j] = acc[cc2][j] + bv;
    }
    __syncthreads();
#pragma unroll 1
    for (int i = tid; i < 4096; i += 128) {
        int co = i >> 5; int p = i & 31;
        out[((size_t)(n * 256 + coBase + co) * H + h) * W + w0 + p] = so[co * 36 + p];
    }
}

// ---------------- GroupNorm stats -> per-(n,c) scale/shift ----------------
// grid: 128 = 8 images * 16 groups; block 256.  SRC: 1 = g_bufA, 2 = g_bufB.
template<int SRC>
__global__ void gn_stats(const float* __restrict__ gamma, const float* __restrict__ beta,
                         int HW)
{
    const float* __restrict__ y = (SRC == 1) ? g_bufA : g_bufB;
    const int n = blockIdx.x >> 4;
    const int g = blockIdx.x & 15;
    const int tid = threadIdx.x;
    float s = 0.f, q = 0.f;
#pragma unroll 1
    for (int c = 0; c < 16; c++) {
        const float4* p = reinterpret_cast<const float4*>(
            y + (size_t)(n * 256 + g * 16 + c) * HW);
#pragma unroll 1
        for (int i = tid; i < (HW >> 2); i += 256) {
            float4 v = p[i];
            s += v.x + v.y + v.z + v.w;
            q += v.x * v.x + v.y * v.y + v.z * v.z + v.w * v.w;
        }
    }
    __shared__ float ss[256], sq[256];
    ss[tid] = s; sq[tid] = q;
    __syncthreads();
    for (int st = 128; st > 0; st >>= 1) {
        if (tid < st) { ss[tid] += ss[tid + st]; sq[tid] += sq[tid + st]; }
        __syncthreads();
    }
    if (tid < 16) {
        float cnt  = 16.f * (float)HW;
        float mean = ss[0] / cnt;
        float var  = sq[0] / cnt - mean * mean;
        float rstd = rsqrtf(var + 1e-5f);
        int c = g * 16 + tid;
        float ga = gamma[c] * rstd;
        g_sa[n * 256 + c] = ga;
        g_sb[n * 256 + c] = beta[c] - mean * ga;
    }
}

// ---------------- classification head: conv 256->20, NHWC concat output ----------------
// reads g_bufB with fused GN+ReLU (g_sa/g_sb)
__global__ __launch_bounds__(128)
void head_cls(const float* __restrict__ w, const float* __restrict__ bias,
              float* __restrict__ out, int H, int W, int lvl_off)
{
    const float* __restrict__ in = g_bufB;
    __shared__ float ws[72 * 20];
    __shared__ float in_s[8 * 3 * 36];
    const int tid  = threadIdx.x;
    const int lane = tid & 31;
    const int pg   = tid >> 5;
    const int tilesW   = W >> 5;
    const int tilesImg = H * tilesW;
    const int n  = blockIdx.x / tilesImg;
    int rem      = blockIdx.x - n * tilesImg;
    const int h  = rem / tilesW;
    const int w0 = (rem - h * tilesW) << 5;

    float acc[8];
#pragma unroll
    for (int j = 0; j < 8; j++) acc[j] = 0.f;

#pragma unroll 1
    for (int ch = 0; ch < 32; ch++) {
        const int c0 = ch << 3;
        __syncthreads();
        if (tid < 20) {
            const float4* wg = reinterpret_cast<const float4*>(
                w + (size_t)tid * 2304 + c0 * 9);
#pragma unroll
            for (int m = 0; m < 18; m++) {
                float4 v = wg[m];
                ws[(4*m + 0) * 20 + tid] = v.x;
                ws[(4*m + 1) * 20 + tid] = v.y;
                ws[(4*m + 2) * 20 + tid] = v.z;
                ws[(4*m + 3) * 20 + tid] = v.w;
            }
        }
#pragma unroll 1
        for (int i = tid; i < 816; i += 128) {
            int ci = i / 102; int r2 = i - ci * 102;
            int rr = r2 / 34;  int cc = r2 - rr * 34;
            int hin = h + rr - 1;
            int win = w0 + cc - 1;
            float v = 0.f;
            if ((unsigned)hin < (unsigned)H && (unsigned)win < (unsigned)W) {
                int cx = n * 256 + c0 + ci;
                v = in[((size_t)cx * H + hin) * W + win];
                v = fmaxf(0.f, fmaf(g_sa[cx], v, g_sb[cx]));
            }
            in_s[(ci * 3 + rr) * 36 + cc] = v;
        }
        __syncthreads();
        if (lane < 20) {
#pragma unroll 1
            for (int ci = 0; ci < 8; ci++) {
#pragma unroll
                for (int kh = 0; kh < 3; kh++) {
                    const float* row = &in_s[(ci * 3 + kh) * 36 + pg * 8];
                    float r[10];
#pragma unroll
                    for (int x = 0; x < 10; x++) r[x] = row[x];
#pragma unroll
                    for (int kw = 0; kw < 3; kw++) {
                        float wv = ws[(ci * 9 + kh * 3 + kw) * 20 + lane];
#pragma unroll
                        for (int j = 0; j < 8; j++)
                            acc[j] = fmaf(wv, r[j + kw], acc[j]);
                    }
                }
            }
        }
    }
    if (lane < 20) {
        float bv = bias[lane];
#pragma unroll
        for (int j = 0; j < 8; j++) {
            int pos = lvl_off + h * W + w0 + pg * 8 + j;
            out[CLSBASE + ((size_t)n * TOTHW + pos) * 20 + lane] = acc[j] + bv;
        }
    }
}

// ---------------- regression head: bbox (4, ReLU) + centerness (1) ----------------
__global__ __launch_bounds__(128)
void head_reg(const float* __restrict__ wreg, const float* __restrict__ breg,
              const float* __restrict__ wctr, const float* __restrict__ bctr,
              float* __restrict__ out, int H, int W, int lvl_off)
{
    const float* __restrict__ in = g_bufB;
    __shared__ float ws[72 * 5];
    __shared__ float in_s[8 * 3 * 36];
    const int tid  = threadIdx.x;
    const int lane = tid & 31;
    const int pg   = tid >> 5;
    const int tilesW   = W >> 5;
    const int tilesImg = H * tilesW;
    const int n  = blockIdx.x / tilesImg;
    int rem      = blockIdx.x - n * tilesImg;
    const int h  = rem / tilesW;
    const int w0 = (rem - h * tilesW) << 5;

    float acc[8];
#pragma unroll
    for (int j = 0; j < 8; j++) acc[j] = 0.f;

#pragma unroll 1
    for (int ch = 0; ch < 32; ch++) {
        const int c0 = ch << 3;
        __syncthreads();
        if (tid < 5) {
            const float* src = (tid < 4) ? (wreg + (size_t)tid * 2304) : wctr;
            const float4* wg = reinterpret_cast<const float4*>(src + c0 * 9);
#pragma unroll
            for (int m = 0; m < 18; m++) {
                float4 v = wg[m];
                ws[(4*m + 0) * 5 + tid] = v.x;
                ws[(4*m + 1) * 5 + tid] = v.y;
                ws[(4*m + 2) * 5 + tid] = v.z;
                ws[(4*m + 3) * 5 + tid] = v.w;
            }
        }
#pragma unroll 1
        for (int i = tid; i < 816; i += 128) {
            int ci = i / 102; int r2 = i - ci * 102;
            int rr = r2 / 34;  int cc = r2 - rr * 34;
            int hin = h + rr - 1;
            int win = w0 + cc - 1;
            float v = 0.f;
            if ((unsigned)hin < (unsigned)H && (unsigned)win < (unsigned)W) {
                int cx = n * 256 + c0 + ci;
                v = in[((size_t)cx * H + hin) * W + win];
                v = fmaxf(0.f, fmaf(g_sa[cx], v, g_sb[cx]));
            }
            in_s[(ci * 3 + rr) * 36 + cc] = v;
        }
        __syncthreads();
        if (lane < 5) {
#pragma unroll 1
            for (int ci = 0; ci < 8; ci++) {
#pragma unroll
                for (int kh = 0; kh < 3; kh++) {
                    const float* row = &in_s[(ci * 3 + kh) * 36 + pg * 8];
                    float r[10];
#pragma unroll
                    for (int x = 0; x < 10; x++) r[x] = row[x];
#pragma unroll
                    for (int kw = 0; kw < 3; kw++) {
                        float wv = ws[(ci * 9 + kh * 3 + kw) * 5 + lane];
#pragma unroll
                        for (int j = 0; j < 8; j++)
                            acc[j] = fmaf(wv, r[j + kw], acc[j]);
                    }
                }
            }
        }
    }
    if (lane < 5) {
#pragma unroll
        for (int j = 0; j < 8; j++) {
            int pos = lvl_off + h * W + w0 + pg * 8 + j;
            if (lane < 4) {
                float v = fmaxf(acc[j] + breg[lane], 0.f);
                out[REGBASE + (size_t)n * (TOTHW * 4) + (size_t)pos * 4 + lane] = v;
            } else {
                out[CTRBASE + (size_t)n * TOTHW + pos] = acc[j] + bctr[0];
            }
        }
    }
}

// ---------------- launch: kernel launches ONLY ----------------
extern "C" void kernel_launch(void* const* d_in, const int* in_sizes, int n_in,
                              void* d_out, int out_size)
{
    const float* feat[3] = {(const float*)d_in[0], (const float*)d_in[1], (const float*)d_in[2]};
    const float* cls_w  = (const float*)d_in[3];
    const float* cls_b  = (const float*)d_in[4];
    const float* cls_gg = (const float*)d_in[5];
    const float* cls_gb = (const float*)d_in[6];
    const float* cls_ow = (const float*)d_in[7];
    const float* cls_ob = (const float*)d_in[8];
    const float* reg_w  = (const float*)d_in[9];
    const float* reg_b  = (const float*)d_in[10];
    const float* reg_gg = (const float*)d_in[11];
    const float* reg_gb = (const float*)d_in[12];
    const float* reg_ow = (const float*)d_in[13];
    const float* reg_ob = (const float*)d_in[14];
    const float* ctr_w  = (const float*)d_in[15];
    const float* ctr_b  = (const float*)d_in[16];
    float* out = (float*)d_out;

    const int Hs[3]   = {100, 50, 25};
    const int Ws[3]   = {128, 64, 32};
    const int offs[3] = {0, 12800, 16000};
    const int N = 8;

    for (int l = 0; l < 3; l++) {
        int H = Hs[l], W = Ws[l], HW = H * W, off = offs[l];
        dim3 gc(N * H * (W / 32), 2);
        dim3 gh(N * H * (W / 32));
        // classification tower
        conv_cc<0><<<gc, 128>>>(feat[l], cls_w, cls_b, H, W);
        gn_stats<1><<<128, 256>>>(cls_gg, cls_gb, HW);
        conv_cc<1><<<gc, 128>>>(nullptr, cls_w + 589824, cls_b + 256, H, W);
        gn_stats<2><<<128, 256>>>(cls_gg + 256, cls_gb + 256, HW);
        head_cls<<<gh, 128>>>(cls_ow, cls_ob, out, H, W, off);
        // regression tower
        conv_cc<0><<<gc, 128>>>(feat[l], reg_w, reg_b, H, W);
        gn_stats<1><<<128, 256>>>(reg_gg, reg_gb, HW);
        conv_cc<1><<<gc, 128>>>(nullptr, reg_w + 589824, reg_b + 256, H, W);
        gn_stats<2><<<128, 256>>>(reg_gg + 256, reg_gb + 256, HW);
        head_reg<<<gh, 128>>>(reg_ow, reg_ob, ctr_w, ctr_b, out, H, W, off);
    }
}